// round 17
// baseline (speedup 1.0000x reference)
#include <cuda_runtime.h>
#include <cstdint>

// Problem constants (fixed by setup_inputs)
#define BB 8
#define CC 256
#define HH 128
#define WW 96
#define HW (HH*WW)

// -------- scratch (device globals; no allocation allowed) --------
__device__ float g_corr[BB*49*HH*WW];   // lrelu(correlation)
__device__ float g_h1[BB*128*HH*WW];
__device__ float g_h2[BB*64*HH*WW];
__device__ float g_h3[BB*32*HH*WW];
__device__ float g_flow[BB*2*HH*WW];

__device__ __forceinline__ float lrelu_f(float v) { return v > 0.f ? v : 0.1f * v; }

// mma.sync m16n8k8 tf32, fp32 accumulate (raw f32 regs; HW uses tf32 bits)
__device__ __forceinline__ void mma_tf32(float* d, const uint32_t* a, const uint32_t* b) {
    asm volatile(
        "mma.sync.aligned.m16n8k8.row.col.f32.tf32.tf32.f32 "
        "{%0,%1,%2,%3}, {%4,%5,%6,%7}, {%8,%9}, {%0,%1,%2,%3};"
        : "+f"(d[0]), "+f"(d[1]), "+f"(d[2]), "+f"(d[3])
        : "r"(a[0]), "r"(a[1]), "r"(a[2]), "r"(a[3]),
          "r"(b[0]), "r"(b[1]));
}

// -------- cp.async helpers --------
__device__ __forceinline__ void cp_async4(uint32_t dst, const float* src, bool v) {
    asm volatile("cp.async.ca.shared.global [%0], [%1], 4, %2;"
                 :: "r"(dst), "l"(src), "r"(v ? 4u : 0u));
}
__device__ __forceinline__ void cp_async16(uint32_t dst, const float* src, bool v) {
    asm volatile("cp.async.cg.shared.global [%0], [%1], 16, %2;"
                 :: "r"(dst), "l"(src), "r"(v ? 16u : 0u));
}
__device__ __forceinline__ void cp_commit() {
    asm volatile("cp.async.commit_group;");
}
template<int N> __device__ __forceinline__ void cp_wait() {
    asm volatile("cp.async.wait_group %0;" :: "n"(N));
}

// ============================================================================
// Correlation — 2 pixels per thread, float4 cp.async loader.
// Block = 192 thr = 4 rows x 48 pixel-pairs. Window = 10 rows, gw -4..99
// (26 float4 per row; fully-OOB edge f4s zero-filled). smem idx = gw + 4.
// Double-buffered over ci-chunks of 4, single sync per chunk.
// ============================================================================
#define CKC 4
__global__ __launch_bounds__(192) void corr_kernel(
    const float* __restrict__ f1, const float* __restrict__ f2,
    float* __restrict__ out)
{
    const int tid = threadIdx.x;
    const int t   = tid % 48;           // pixel pair -> pixels 2t, 2t+1
    const int r   = tid / 48;           // 0..3
    const int h0  = blockIdx.x * 4;
    const int b   = blockIdx.y;
    const int h   = h0 + r;

    __shared__ float s2[2][CKC*10*112]; // [stage][ci][row 10][idx 112]

    float acc0[49], acc1[49];
#pragma unroll
    for (int i = 0; i < 49; ++i) { acc0[i] = 0.f; acc1[i] = 0.f; }

    // ---- hoisted loader slots: float4 j = tid + 192*s over 10x26 grid ----
    int  dstS[2], goffS[2];
    bool inbS[2], haveS[2];
#pragma unroll
    for (int s = 0; s < 2; ++s) {
        int j = tid + 192*s;
        haveS[s] = j < 260;
        int rr  = j / 26;
        int q   = j - 26*rr;            // f4 col: gw = 4q - 4 .. 4q - 1
        int gh  = h0 + rr - 3;
        int gwS = 4*q - 4;
        inbS[s]  = (unsigned)gh < (unsigned)HH && q >= 1 && q <= 24;
        goffS[s] = gh*WW + gwS;
        dstS[s]  = rr*112 + 4*q;        // idx = gw + 4
    }
    const float* f1p = f1 + ((size_t)b*CC*HH + h)*WW + 2*t;

    auto issue = [&](int c0, int bf) {
        const uint32_t sb = (uint32_t)__cvta_generic_to_shared(&s2[bf][0]);
        const float* f2b = f2 + ((size_t)b*CC + c0)*HW;
#pragma unroll
        for (int ci = 0; ci < CKC; ++ci) {
#pragma unroll
            for (int s = 0; s < 2; ++s) {
                if (haveS[s]) {
                    bool v = inbS[s];
                    cp_async16(sb + (uint32_t)(ci*1120 + dstS[s])*4u,
                               v ? f2b + (size_t)ci*HW + goffS[s] : f2, v);
                }
            }
        }
    };

    issue(0, 0);
    cp_commit();

    int buf = 0;
    for (int c0 = 0; c0 < CC; c0 += CKC) {
        cp_wait<0>();
        __syncthreads();
        if (c0 + CKC < CC) {
            issue(c0 + CKC, buf ^ 1);
            cp_commit();
        }
#pragma unroll
        for (int ci = 0; ci < CKC; ++ci) {
            float2 av = *reinterpret_cast<const float2*>(f1p + (size_t)(c0 + ci)*HW);
            const float* s2c = &s2[buf][ci*1120];
#pragma unroll
            for (int dy = 0; dy < 7; ++dy) {
                // load idx 2t..2t+9; window for p0: idx 2t+1..2t+7, p1: 2t+2..2t+8
                const float2* rp = reinterpret_cast<const float2*>(s2c + (r + dy)*112 + 2*t);
                float2 p0 = rp[0], p1 = rp[1], p2 = rp[2], p3 = rp[3], p4 = rp[4];
                float rr_[10] = { p0.x, p0.y, p1.x, p1.y, p2.x, p2.y,
                                  p3.x, p3.y, p4.x, p4.y };
#pragma unroll
                for (int dx = 0; dx < 7; ++dx) {
                    acc0[dy*7 + dx] += av.x * rr_[dx + 1];
                    acc1[dy*7 + dx] += av.y * rr_[dx + 2];
                }
            }
        }
        buf ^= 1;
    }

#pragma unroll
    for (int o = 0; o < 49; ++o) {
        float2 v;
        v.x = lrelu_f(acc0[o] * (1.0f/256.0f));
        v.y = lrelu_f(acc1[o] * (1.0f/256.0f));
        *reinterpret_cast<float2*>(out + (((size_t)b*49 + o)*HH + h)*WW + 2*t) = v;
    }
}

// ============================================================================
// 3x3 conv — tf32 mma.sync implicit GEMM, cp.async double-buffered (CK=8).
// 2 output rows per warp: block tile = 32 couts x 8h x 32w, 128 thr (4 warps).
// Input loader: float4 cp.async (row gw = w0-4 .. w0+35; edge f4s zero-fill).
// smem: s_in [ci][row 10][40+pad]  S=424 (424%32==8 -> B frags conflict-free)
//       s_w  [ci][tap][co 32]      CIS=296 (296%32==8 -> A frags conflict-free)
// Single sync per chunk: wait -> sync -> issue(next) -> compute.
// ============================================================================
template<int CIN, int COUT, bool RELU>
__global__ __launch_bounds__(128, 4) void conv3x3_mma(
    const float* __restrict__ x, const float* __restrict__ wgt,
    const float* __restrict__ bias, float* __restrict__ y)
{
    constexpr int CK  = 8;
    constexpr int R   = 40;             // row stride (floats), f4-aligned
    constexpr int S   = 10 * R + 24;    // 424: ci stride in s_in
    constexpr int WS  = 32;             // tap stride in s_w
    constexpr int CIS = 9 * WS + 8;     // 296: ci stride in s_w
    constexpr int NCH = (CIN + CK - 1) / CK;

    __shared__ float s_in[2][CK * S];    // 2 x 13568 B
    __shared__ float s_w [2][CK * CIS];  // 2 x 9472 B

    const int tid  = threadIdx.x;
    const int warp = tid >> 5;
    const int lane = tid & 31;

    const int w0 = blockIdx.x * 32;
    const int h0 = blockIdx.y * 8;
    constexpr int NCO = COUT / 32;
    const int co0 = (blockIdx.z % NCO) * 32;
    const int b   = blockIdx.z / NCO;

    float d[2][2][4][4];                 // [m][row][nt][frag]
#pragma unroll
    for (int m = 0; m < 2; ++m)
#pragma unroll
        for (int rr2 = 0; rr2 < 2; ++rr2)
#pragma unroll
            for (int n = 0; n < 4; ++n)
#pragma unroll
                for (int k = 0; k < 4; ++k) d[m][rr2][n][k] = 0.f;

    // ---- hoisted input-loader slot: one float4 per thread per ci ----
    // j = tid over 10 rows x 10 f4-cols; gw = w0-4+4q .. w0-1+4q
    const bool haveI = tid < 100;
    int  dstI = 0, goffI = 0;
    bool inbI = false;
    {
        int j  = tid < 100 ? tid : 0;
        int rr = j / 10;
        int q  = j - 10*rr;
        int gh  = h0 + rr - 1;
        int gwS = w0 - 4 + 4*q;
        inbI  = (unsigned)gh < (unsigned)HH && gwS >= 0 && (gwS + 3) < WW;
        goffI = gh*WW + gwS;
        dstI  = rr*R + 4*q;             // idx = gw - (w0-4)
    }

    // weight loader role: thread -> co = tid>>2, sub-lane j = tid&3
    const int l_co = tid >> 2;
    const int l_j  = tid & 3;
    const float* wbase = wgt + (size_t)(co0 + l_co)*CIN*9;

    auto issue = [&](int c0, int bf) {
        uint32_t sb_in = (uint32_t)__cvta_generic_to_shared(&s_in[bf][0]);
        uint32_t sb_w  = (uint32_t)__cvta_generic_to_shared(&s_w[bf][0]);
        const float* xb = x + ((size_t)b*CIN + c0)*HW;
        const float* wp = wbase + (size_t)c0*9;
#pragma unroll
        for (int ci = 0; ci < CK; ++ci) {
            bool cv = (c0 + ci) < CIN;
            if (haveI) {
                bool v = cv && inbI;
                cp_async16(sb_in + (uint32_t)(ci*S + dstI)*4u,
                           v ? xb + (size_t)ci*HW + goffI : x, v);
            }
#pragma unroll
            for (int t = 0; t < 3; ++t) {
                int tap = l_j + 4*t;
                if (tap < 9)
                    cp_async4(sb_w + (uint32_t)(ci*CIS + tap*WS + l_co)*4u,
                              cv ? wp + ci*9 + tap : wgt, cv);
            }
        }
    };

    issue(0, 0);
    cp_commit();

    int buf = 0;
    for (int ch = 0; ch < NCH; ++ch) {
        cp_wait<0>();
        __syncthreads();
        if (ch + 1 < NCH) {
            issue((ch + 1)*CK, buf ^ 1);
            cp_commit();
        }

        const uint32_t* si  = (const uint32_t*)&s_in[buf][0];
        const uint32_t* swp = (const uint32_t*)&s_w[buf][0];

        const int ciA = lane & 3;
        const int coA = lane >> 2;
        const int nB  = lane >> 2;

#pragma unroll
        for (int ky = 0; ky < 3; ++ky) {
#pragma unroll
            for (int kx = 0; kx < 3; ++kx) {
                const int tap = ky*3 + kx;
                // ---- A fragments (weights), shared by both rows ----
                uint32_t a[2][4];
#pragma unroll
                for (int m = 0; m < 2; ++m) {
                    int cob = m*16 + coA;
                    a[m][0] = swp[ ciA   *CIS + tap*WS + cob    ];
                    a[m][1] = swp[ ciA   *CIS + tap*WS + cob + 8];
                    a[m][2] = swp[(ciA+4)*CIS + tap*WS + cob    ];
                    a[m][3] = swp[(ciA+4)*CIS + tap*WS + cob + 8];
                }
                // ---- B fragments, 2 rows; smem idx = n + kx + 3 ----
#pragma unroll
                for (int rr2 = 0; rr2 < 2; ++rr2) {
                    const int row = 2*warp + rr2 + ky;
                    const uint32_t* bbase = si + ciA*S + row*R + nB + kx + 3;
#pragma unroll
                    for (int nt = 0; nt < 4; ++nt) {
                        uint32_t bf[2];
                        bf[0] = bbase[nt*8];
                        bf[1] = bbase[nt*8 + 4*S];
                        mma_tf32(d[0][rr2][nt], a[0], bf);
                        mma_tf32(d[1][rr2][nt], a[1], bf);
                    }
                }
            }
        }
        buf ^= 1;
    }

    // ---- epilogue (STG.64 pairs) ----
#pragma unroll
    for (int m = 0; m < 2; ++m) {
        int co  = co0 + m*16 + (lane >> 2);
        float bv0 = bias[co];
        float bv1 = bias[co + 8];
#pragma unroll
        for (int rr2 = 0; rr2 < 2; ++rr2) {
            int h = h0 + 2*warp + rr2;
#pragma unroll
            for (int nt = 0; nt < 4; ++nt) {
                int wc = w0 + nt*8 + (lane & 3)*2;
                float v0 = d[m][rr2][nt][0] + bv0;
                float v1 = d[m][rr2][nt][1] + bv0;
                float v2 = d[m][rr2][nt][2] + bv1;
                float v3 = d[m][rr2][nt][3] + bv1;
                if (RELU) {
                    v0 = lrelu_f(v0); v1 = lrelu_f(v1);
                    v2 = lrelu_f(v2); v3 = lrelu_f(v3);
                }
                float* yp = y + (((size_t)b*COUT + co)*HH + h)*WW + wc;
                *reinterpret_cast<float2*>(yp)        = make_float2(v0, v1);
                *reinterpret_cast<float2*>(yp + 8*HW) = make_float2(v2, v3);
            }
        }
    }
}

// ============================================================================
// Final 3x3 conv 32 -> 2 (flow). Unchanged.
// ============================================================================
__global__ __launch_bounds__(256) void conv_last_kernel(
    const float* __restrict__ x, const float* __restrict__ wgt,
    const float* __restrict__ bias, float* __restrict__ flow)
{
    __shared__ float sw[2*32*9];
    for (int i = threadIdx.x; i < 2*32*9; i += 256) sw[i] = wgt[i];
    __syncthreads();

    int idx = blockIdx.x*256 + threadIdx.x;
    int w = idx % WW;
    int h = (idx / WW) % HH;
    int b = idx / (WW*HH);

    float a0 = bias[0], a1 = bias[1];
    for (int ci = 0; ci < 32; ++ci) {
        const float* xp = x + ((size_t)(b*32 + ci))*HW;
        const float* w0p = &sw[(0*32 + ci)*9];
        const float* w1p = &sw[(1*32 + ci)*9];
#pragma unroll
        for (int ky = 0; ky < 3; ++ky) {
            int gh = h + ky - 1;
            if ((unsigned)gh >= (unsigned)HH) continue;
#pragma unroll
            for (int kx = 0; kx < 3; ++kx) {
                int gw = w + kx - 1;
                if ((unsigned)gw >= (unsigned)WW) continue;
                float v = xp[gh*WW + gw];
                a0 += v * w0p[ky*3 + kx];
                a1 += v * w1p[ky*3 + kx];
            }
        }
    }
    flow[((size_t)b*2*HH + h)*WW + w]        = a0;
    flow[(((size_t)b*2 + 1)*HH + h)*WW + w]  = a1;
}

// ============================================================================
// apply_offset + grid_sample fused (per-pixel math hoisted). Unchanged.
// ============================================================================
__global__ __launch_bounds__(384) void warp_kernel(
    const float* __restrict__ f2, const float* __restrict__ flow,
    float* __restrict__ out)
{
    const int tid = threadIdx.x;
    const int w   = tid % 96;
    const int cs  = tid / 96;            // 0..3 -> channels cs*64 .. cs*64+63
    const int h   = blockIdx.x;
    const int b   = blockIdx.y;

    float fx = flow[((size_t)b*2*HH + h)*WW + w];
    float fy = flow[(((size_t)b*2 + 1)*HH + h)*WW + w];

    float xx = fminf(fmaxf((float)w + fx, 0.f), (float)(WW-1));
    float yy = fminf(fmaxf((float)h + fy, 0.f), (float)(HH-1));
    float x0f = floorf(xx), y0f = floorf(yy);
    float wx = xx - x0f,  wy = yy - y0f;
    int x0 = (int)x0f, y0 = (int)y0f;
    int x1 = min(x0 + 1, WW-1);
    int y1 = min(y0 + 1, HH-1);

    const float w00 = (1.f-wx)*(1.f-wy);
    const float w01 = wx*(1.f-wy);
    const float w10 = (1.f-wx)*wy;
    const float w11 = wx*wy;

    const int i00 = y0*WW + x0;
    const int i01 = y0*WW + x1;
    const int i10 = y1*WW + x0;
    const int i11 = y1*WW + x1;

    const float* base = f2  + ((size_t)b*CC + cs*64)*HW;
    float*       op   = out + ((size_t)b*CC + cs*64)*HW + h*WW + w;

#pragma unroll 4
    for (int c = 0; c < 64; ++c) {
        const float* pp = base + (size_t)c*HW;
        float v = pp[i00]*w00 + pp[i01]*w01 + pp[i10]*w10 + pp[i11]*w11;
        op[(size_t)c*HW] = v;
    }
}

// ============================================================================
// launch
// ============================================================================
extern "C" void kernel_launch(void* const* d_in, const int* in_sizes, int n_in,
                              void* d_out, int out_size)
{
    const float* feat1 = (const float*)d_in[0];
    const float* feat2 = (const float*)d_in[1];
    const float* w1 = (const float*)d_in[2];
    const float* b1 = (const float*)d_in[3];
    const float* w2 = (const float*)d_in[4];
    const float* b2 = (const float*)d_in[5];
    const float* w3 = (const float*)d_in[6];
    const float* b3 = (const float*)d_in[7];
    const float* w4 = (const float*)d_in[8];
    const float* b4 = (const float*)d_in[9];
    float* out = (float*)d_out;

    float *p_corr, *p_h1, *p_h2, *p_h3, *p_flow;
    cudaGetSymbolAddress((void**)&p_corr, g_corr);
    cudaGetSymbolAddress((void**)&p_h1,   g_h1);
    cudaGetSymbolAddress((void**)&p_h2,   g_h2);
    cudaGetSymbolAddress((void**)&p_h3,   g_h3);
    cudaGetSymbolAddress((void**)&p_flow, g_flow);

    corr_kernel<<<dim3(HH/4, BB), 192>>>(feat1, feat2, p_corr);

    conv3x3_mma<49, 128, true><<<dim3(3, 16, BB*4), 128>>>(p_corr, w1, b1, p_h1);
    conv3x3_mma<128, 64, true><<<dim3(3, 16, BB*2), 128>>>(p_h1,  w2, b2, p_h2);
    conv3x3_mma<64,  32, true><<<dim3(3, 16, BB*1), 128>>>(p_h2,  w3, b3, p_h3);

    conv_last_kernel<<<(BB*HH*WW)/256, 256>>>(p_h3, w4, b4, p_flow);

    warp_kernel<<<dim3(HH, BB), 384>>>(feat2, p_flow, out);
}